// round 5
// baseline (speedup 1.0000x reference)
#include <cuda_runtime.h>

// ---------------------------------------------------------------------------
// DNN_SKalmanNet_GSS — batch-1 GEMV chain, HBM-bound (~499 MB weights/pass).
// 4 launches:
//   K1: input built in smem per block + l1/l3 GEMV (relu)        [~46 MB]
//   K2: GRU gi/gh GEMV, 4 segments                               [~352 MB]
//   K3: gate fused into staging + l2_W1/l4_W1 GEMV (relu)        [~67 MB]
//   K4: l2_W2/l4_W2 GEMV -> d_out                                [~34 MB]
// Inner loop: 8-deep manual pipeline (8 float4 W loads in regs) to maximize
// MLP; 4 accumulators; x staged in shared memory.
// ---------------------------------------------------------------------------

#define H1   5120
#define H2   4096
#define HID  2048
#define IN1  1120

__device__ float g_l1[H1];
__device__ float g_l3[H1];
__device__ float g_gi1[3 * HID];
__device__ float g_gh1[3 * HID];
__device__ float g_gi2[3 * HID];
__device__ float g_gh2[3 * HID];
__device__ float g_hid1[H2];
__device__ float g_hid2[H2];

// Warp-per-row GEMV; x staged in smem as float4. 8-deep load pipeline.
__device__ __forceinline__ void gemv_core(const float* __restrict__ W,
                                          const float* __restrict__ b,
                                          float* __restrict__ y,
                                          int rows, int c4, int act,
                                          const float4* __restrict__ sx) {
    const int lane = threadIdx.x & 31;
    const int warp = (blockIdx.x * blockDim.x + threadIdx.x) >> 5;
    const int nw   = (gridDim.x * blockDim.x) >> 5;
    for (int row = warp; row < rows; row += nw) {
        const float4* __restrict__ Wr = (const float4*)W + (size_t)row * c4;
        float a0 = 0.f, a1 = 0.f, a2 = 0.f, a3 = 0.f;
        int j = lane;
        // Main loop: 8 independent float4 loads in flight per warp
        for (; j + 224 < c4; j += 256) {
            float4 w0 = Wr[j];
            float4 w1 = Wr[j +  32];
            float4 w2 = Wr[j +  64];
            float4 w3 = Wr[j +  96];
            float4 w4 = Wr[j + 128];
            float4 w5 = Wr[j + 160];
            float4 w6 = Wr[j + 192];
            float4 w7 = Wr[j + 224];
            float4 x0 = sx[j];
            float4 x1 = sx[j +  32];
            float4 x2 = sx[j +  64];
            float4 x3 = sx[j +  96];
            a0 = fmaf(w0.x, x0.x, a0); a1 = fmaf(w0.y, x0.y, a1);
            a2 = fmaf(w0.z, x0.z, a2); a3 = fmaf(w0.w, x0.w, a3);
            a0 = fmaf(w1.x, x1.x, a0); a1 = fmaf(w1.y, x1.y, a1);
            a2 = fmaf(w1.z, x1.z, a2); a3 = fmaf(w1.w, x1.w, a3);
            a0 = fmaf(w2.x, x2.x, a0); a1 = fmaf(w2.y, x2.y, a1);
            a2 = fmaf(w2.z, x2.z, a2); a3 = fmaf(w2.w, x2.w, a3);
            a0 = fmaf(w3.x, x3.x, a0); a1 = fmaf(w3.y, x3.y, a1);
            a2 = fmaf(w3.z, x3.z, a2); a3 = fmaf(w3.w, x3.w, a3);
            float4 x4 = sx[j + 128];
            float4 x5 = sx[j + 160];
            float4 x6 = sx[j + 192];
            float4 x7 = sx[j + 224];
            a0 = fmaf(w4.x, x4.x, a0); a1 = fmaf(w4.y, x4.y, a1);
            a2 = fmaf(w4.z, x4.z, a2); a3 = fmaf(w4.w, x4.w, a3);
            a0 = fmaf(w5.x, x5.x, a0); a1 = fmaf(w5.y, x5.y, a1);
            a2 = fmaf(w5.z, x5.z, a2); a3 = fmaf(w5.w, x5.w, a3);
            a0 = fmaf(w6.x, x6.x, a0); a1 = fmaf(w6.y, x6.y, a1);
            a2 = fmaf(w6.z, x6.z, a2); a3 = fmaf(w6.w, x6.w, a3);
            a0 = fmaf(w7.x, x7.x, a0); a1 = fmaf(w7.y, x7.y, a1);
            a2 = fmaf(w7.z, x7.z, a2); a3 = fmaf(w7.w, x7.w, a3);
        }
        for (; j < c4; j += 32) {
            float4 w = Wr[j];
            float4 x = sx[j];
            a0 = fmaf(w.x, x.x, a0); a1 = fmaf(w.y, x.y, a1);
            a2 = fmaf(w.z, x.z, a2); a3 = fmaf(w.w, x.w, a3);
        }
        float acc = (a0 + a1) + (a2 + a3);
        #pragma unroll
        for (int o = 16; o; o >>= 1) acc += __shfl_xor_sync(0xffffffffu, acc, o);
        if (lane == 0) {
            float v = acc + b[row];
            if (act) v = fmaxf(v, 0.f);
            y[row] = v;
        }
    }
}

extern __shared__ float4 smem_x[];

// K1: build branch input in smem, then l1/l3 GEMV (relu). blockIdx.y = branch.
__global__ void k1_input_gemv(const float* __restrict__ si,
                              const float* __restrict__ oi,
                              const float* __restrict__ ds,
                              const float* __restrict__ dob,
                              const float* __restrict__ le,
                              const float* __restrict__ J,
                              const float* __restrict__ l1W,
                              const float* __restrict__ l1b,
                              const float* __restrict__ l3W,
                              const float* __restrict__ l3b) {
    const int br = blockIdx.y;
    float* s = (float*)smem_x;
    for (int i = threadIdx.x; i < IN1; i += blockDim.x) {
        float v;
        if (i < 32)       v = br ? oi[i]       : si[i];
        else if (i < 64)  v = br ? dob[i - 32] : ds[i - 32];
        else if (i < 96)  v = le[i - 64];
        else              v = J[i - 96];
        s[i] = v;
    }
    __syncthreads();
    gemv_core(br ? l3W : l1W, br ? l3b : l1b, br ? g_l3 : g_l1,
              H1, IN1 / 4, 1, smem_x);
}

// K2: 4-segment GEMV (gi1, gh1, gi2, gh2). blockIdx.y = segment.
struct Seg { const float *W, *x, *b; float* y; int rows, c4; };
struct Segs4 { Seg s[4]; };

__global__ void k2_gru_gemv(Segs4 segs) {
    Seg s = segs.s[blockIdx.y];
    const float4* __restrict__ xv = (const float4*)s.x;
    for (int j = threadIdx.x; j < s.c4; j += blockDim.x) smem_x[j] = xv[j];
    __syncthreads();
    gemv_core(s.W, s.b, s.y, s.rows, s.c4, 0, smem_x);
}

// K3: each block computes full GRU h (2048) from gi/gh/hn into smem, then
// hidden = relu(W1 @ h + b1). blockIdx.y = branch.
__global__ void k3_gate_gemv(const float* __restrict__ hn1,
                             const float* __restrict__ hn2,
                             const float* __restrict__ l2W1,
                             const float* __restrict__ l2b1,
                             const float* __restrict__ l4W1,
                             const float* __restrict__ l4b1) {
    const int br = blockIdx.y;
    const float* __restrict__ gi = br ? g_gi2 : g_gi1;
    const float* __restrict__ gh = br ? g_gh2 : g_gh1;
    const float* __restrict__ hp = br ? hn2 : hn1;
    float* s = (float*)smem_x;
    for (int k = threadIdx.x; k < HID; k += blockDim.x) {
        float r = 1.f / (1.f + __expf(-(gi[k]       + gh[k])));
        float z = 1.f / (1.f + __expf(-(gi[k + HID] + gh[k + HID])));
        float n = tanhf(gi[k + 2 * HID] + r * gh[k + 2 * HID]);
        s[k] = (1.f - z) * n + z * hp[k];
    }
    __syncthreads();
    gemv_core(br ? l4W1 : l2W1, br ? l4b1 : l2b1, br ? g_hid2 : g_hid1,
              H2, HID / 4, 1, smem_x);
}

// K4: out = W2 @ hidden + b2 -> d_out. blockIdx.y = branch.
__global__ void k4_out_gemv(const float* __restrict__ l2W2,
                            const float* __restrict__ l2b2,
                            const float* __restrict__ l4W2,
                            const float* __restrict__ l4b2,
                            float* __restrict__ out) {
    const int br = blockIdx.y;
    const float* __restrict__ x = br ? g_hid2 : g_hid1;
    const float4* __restrict__ xv = (const float4*)x;
    for (int j = threadIdx.x; j < H2 / 4; j += blockDim.x) smem_x[j] = xv[j];
    __syncthreads();
    gemv_core(br ? l4W2 : l2W2, br ? l4b2 : l2b2, out + br * 1024,
              1024, H2 / 4, 0, smem_x);
}

extern "C" void kernel_launch(void* const* d_in, const int* in_sizes, int n_in,
                              void* d_out, int out_size) {
    const float* si    = (const float*)d_in[0];
    const float* oi    = (const float*)d_in[1];
    const float* ds    = (const float*)d_in[2];
    const float* dob   = (const float*)d_in[3];
    const float* le    = (const float*)d_in[4];
    const float* J     = (const float*)d_in[5];
    const float* l1W   = (const float*)d_in[6];
    const float* l1b   = (const float*)d_in[7];
    const float* g1Wih = (const float*)d_in[8];
    const float* g1Whh = (const float*)d_in[9];
    const float* g1bih = (const float*)d_in[10];
    const float* g1bhh = (const float*)d_in[11];
    const float* l2W1  = (const float*)d_in[12];
    const float* l2b1  = (const float*)d_in[13];
    const float* l2W2  = (const float*)d_in[14];
    const float* l2b2  = (const float*)d_in[15];
    const float* l3W   = (const float*)d_in[16];
    const float* l3b   = (const float*)d_in[17];
    const float* g2Wih = (const float*)d_in[18];
    const float* g2Whh = (const float*)d_in[19];
    const float* g2bih = (const float*)d_in[20];
    const float* g2bhh = (const float*)d_in[21];
    const float* l4W1  = (const float*)d_in[22];
    const float* l4b1  = (const float*)d_in[23];
    const float* l4W2  = (const float*)d_in[24];
    const float* l4b2  = (const float*)d_in[25];
    const float* hn1   = (const float*)d_in[26];
    const float* hn2   = (const float*)d_in[27];
    float* out = (float*)d_out;

    float *p_l1, *p_l3, *p_gi1, *p_gh1, *p_gi2, *p_gh2;
    cudaGetSymbolAddress((void**)&p_l1,  g_l1);
    cudaGetSymbolAddress((void**)&p_l3,  g_l3);
    cudaGetSymbolAddress((void**)&p_gi1, g_gi1);
    cudaGetSymbolAddress((void**)&p_gh1, g_gh1);
    cudaGetSymbolAddress((void**)&p_gi2, g_gi2);
    cudaGetSymbolAddress((void**)&p_gh2, g_gh2);

    // K1: 5120 rows, warp per row -> 640 blocks x 2 branches
    k1_input_gemv<<<dim3(H1 / 8, 2), 256, IN1 * sizeof(float)>>>(
        si, oi, ds, dob, le, J, l1W, l1b, l3W, l3b);

    // K2: 6144 rows x 4 segments -> 768 blocks x 4
    {
        Segs4 sg;
        sg.s[0] = { g1Wih, p_l1, g1bih, p_gi1, 3 * HID, H1 / 4 };
        sg.s[1] = { g1Whh, hn1,  g1bhh, p_gh1, 3 * HID, HID / 4 };
        sg.s[2] = { g2Wih, p_l3, g2bih, p_gi2, 3 * HID, H1 / 4 };
        sg.s[3] = { g2Whh, hn2,  g2bhh, p_gh2, 3 * HID, HID / 4 };
        k2_gru_gemv<<<dim3((3 * HID) / 8, 4), 256, H1 * sizeof(float)>>>(sg);
    }

    // K3: gate fused + 4096 rows -> 512 blocks x 2
    k3_gate_gemv<<<dim3(H2 / 8, 2), 256, HID * sizeof(float)>>>(
        hn1, hn2, l2W1, l2b1, l4W1, l4b1);

    // K4: 1024 rows -> 128 blocks x 2
    k4_out_gemv<<<dim3(1024 / 8, 2), 256, H2 * sizeof(float)>>>(
        l2W2, l2b2, l4W2, l4b2, out);

    (void)in_sizes; (void)n_in; (void)out_size;
}